// round 12
// baseline (speedup 1.0000x reference)
#include <cuda_runtime.h>
#include <cuda_fp16.h>
#include <cstdint>

// Problem constants
#define M_TOK   4096
#define K_IN    3072
#define N_OUT   9216
#define GROUP   64
#define RANK    32
#define NGRP    48            // K_IN / GROUP
#define HEAD_DIM 128
#define N_HEADS 24

// ---------------- scratch (device globals: allocation-free) ----------------
__device__ int8_t g_Aq[(size_t)M_TOK * K_IN];    // quantized activations (int4 in int8)
__device__ int8_t g_Wq[(size_t)N_OUT * K_IN];    // unpacked weights (int4 in int8)
__device__ float  g_AS[(size_t)NGRP * M_TOK];    // act scales, transposed [g][m]
__device__ __half g_LAh[(size_t)M_TOK * RANK];   // lora_act fp16
__device__ __half g_LUh[(size_t)N_OUT * RANK];   // lora_up fp16
__device__ int    g_qw_is_i32;

// ---------------- detect qweight storage dtype ----------------
__global__ void detect_qw_kernel(const int* __restrict__ qw32) {
    int ok = 1;
    for (int i = threadIdx.x; i < 8192; i += 256) {
        int hi = qw32[i] >> 8;
        if (hi != 0 && hi != -1) ok = 0;
    }
    __syncthreads();
    unsigned all = __all_sync(0xffffffffu, ok);
    __shared__ int wall[8];
    if ((threadIdx.x & 31) == 0) wall[threadIdx.x >> 5] = (int)all;
    __syncthreads();
    if (threadIdx.x == 0) {
        int r = 1;
        #pragma unroll
        for (int i = 0; i < 8; i++) r &= wall[i];
        g_qw_is_i32 = r;
    }
}

// ---------------- K0: weight nibble unpack (int8) ----------------
__global__ void unpack_w_kernel(const void* __restrict__ qw_raw) {
    int idx = blockIdx.x * 256 + threadIdx.x;
    const int TOT = N_OUT * (K_IN / 2);
    if (idx >= TOT) return;
    int b;
    if (g_qw_is_i32) b = ((const int*)qw_raw)[idx];
    else             b = ((const int8_t*)qw_raw)[idx];
    char2 v;
    v.x = (char)(((b & 0xF) ^ 8) - 8);
    v.y = (char)((b << 24) >> 28);
    *reinterpret_cast<char2*>(&g_Wq[(size_t)idx * 2]) = v;
}

__global__ void lora_wh_kernel(const float* __restrict__ lup) {
    int n = blockIdx.x;
    int t = threadIdx.x;   // 0..31
    g_LUh[n * RANK + t] = __float2half(lup[n * RANK + t]);
}

// ---------------- K1: activation quant (int8 + scales) + lora_act ----------------
__global__ void quant_act_kernel(const float* __restrict__ x,
                                 const float* __restrict__ smooth,
                                 const float* __restrict__ ldn) {
    __shared__ float xs[K_IN];
    __shared__ float part[8][RANK];
    int m    = blockIdx.x;
    int tid  = threadIdx.x;
    int lane = tid & 31;
    int w    = tid >> 5;

    const float* xr = x + (size_t)m * K_IN;
    for (int i = tid; i < K_IN; i += 256)
        xs[i] = __fdiv_rn(xr[i], smooth[i]);
    __syncthreads();

    #pragma unroll
    for (int j = 0; j < 6; j++) {
        int g  = w + 8 * j;
        int k1 = g * GROUP + lane;
        float v1 = xs[k1], v2 = xs[k1 + 32];
        float amax = fmaxf(fabsf(v1), fabsf(v2));
        #pragma unroll
        for (int o = 16; o > 0; o >>= 1)
            amax = fmaxf(amax, __shfl_xor_sync(0xffffffffu, amax, o));
        float ascale = fmaxf(__fdiv_rn(amax, 7.0f), 1e-8f);
        float q1 = fminf(fmaxf(rintf(__fdiv_rn(v1, ascale)), -8.0f), 7.0f);
        float q2 = fminf(fmaxf(rintf(__fdiv_rn(v2, ascale)), -8.0f), 7.0f);
        g_Aq[(size_t)m * K_IN + k1]      = (int8_t)(int)q1;
        g_Aq[(size_t)m * K_IN + k1 + 32] = (int8_t)(int)q2;
        if (lane == 0) g_AS[(size_t)g * M_TOK + m] = ascale;
    }

    float acc = 0.0f;
    int kbeg = w * (K_IN / 8), kend = kbeg + (K_IN / 8);
    for (int k = kbeg; k < kend; k++)
        acc = fmaf(xs[k], ldn[k * RANK + lane], acc);
    part[w][lane] = acc;
    __syncthreads();
    if (w == 0) {
        float s = 0.0f;
        #pragma unroll
        for (int i = 0; i < 8; i++) s += part[i][lane];
        g_LAh[m * RANK + lane] = __float2half(s);
    }
}

// ---------------- K2: int8 IMMA GEMM 128x256, group fixup, fused lora HMMA ----------------
#define BM 128
#define BN 256
#define BK 64                 // bytes per row per stage = one group
#define BROW 80               // padded row stride bytes
#define NSTAGE 4
#define KT NGRP               // 48
// per-stage layout (bytes)
#define A_OFF   0
#define B_OFF   (BM * BROW)               // 10240
#define ASC_OFF (B_OFF + BN * BROW)       // 30720
#define WSC_OFF (ASC_OFF + BM * 4)        // 31232
#define ST_STRIDE (WSC_OFF + BN * 4 - ASC_OFF + ASC_OFF)  // 32256
#define SMEM_TOTAL (NSTAGE * ST_STRIDE)   // 129024

__device__ __forceinline__ void cp_async16(uint32_t dst, const void* src) {
    asm volatile("cp.async.cg.shared.global [%0], [%1], 16;" :: "r"(dst), "l"(src));
}
__device__ __forceinline__ void ldmx4(uint32_t addr, uint32_t& r0, uint32_t& r1,
                                      uint32_t& r2, uint32_t& r3) {
    asm volatile("ldmatrix.sync.aligned.m8n8.x4.shared.b16 {%0,%1,%2,%3}, [%4];"
                 : "=r"(r0), "=r"(r1), "=r"(r2), "=r"(r3) : "r"(addr));
}
__device__ __forceinline__ void imma16832(int* c, uint32_t a0, uint32_t a1,
                                          uint32_t a2, uint32_t a3,
                                          uint32_t b0, uint32_t b1) {
    asm volatile("mma.sync.aligned.m16n8k32.row.col.s32.s8.s8.s32 "
                 "{%0,%1,%2,%3}, {%4,%5,%6,%7}, {%8,%9}, {%0,%1,%2,%3};"
                 : "+r"(c[0]), "+r"(c[1]), "+r"(c[2]), "+r"(c[3])
                 : "r"(a0), "r"(a1), "r"(a2), "r"(a3), "r"(b0), "r"(b1));
}
__device__ __forceinline__ void hmma16816(float* c, uint32_t a0, uint32_t a1,
                                          uint32_t a2, uint32_t a3,
                                          uint32_t b0, uint32_t b1) {
    asm volatile("mma.sync.aligned.m16n8k16.row.col.f32.f16.f16.f32 "
                 "{%0,%1,%2,%3}, {%4,%5,%6,%7}, {%8,%9}, {%0,%1,%2,%3};"
                 : "+f"(c[0]), "+f"(c[1]), "+f"(c[2]), "+f"(c[3])
                 : "r"(a0), "r"(a1), "r"(a2), "r"(a3), "r"(b0), "r"(b1));
}

__global__ void __launch_bounds__(256, 1)
gemm_kernel(float* __restrict__ out, const float* __restrict__ bias,
            const float* __restrict__ wsc) {
    extern __shared__ char smem[];
    uint32_t sbase;
    asm("{ .reg .u64 t; cvta.to.shared.u64 t, %1; cvt.u32.u64 %0, t; }"
        : "=r"(sbase) : "l"(smem));

    const int tid  = threadIdx.x;
    const int lane = tid & 31;
    const int w    = tid >> 5;
    const int wm   = (w >> 2) * 64;    // 2 warps in m
    const int wn   = (w & 3) * 64;     // 4 warps in n
    const int m0   = blockIdx.y * BM;
    const int n0   = blockIdx.x * BN;

    auto load_stage = [&](int s, int kb) {
        const uint32_t st = sbase + s * ST_STRIDE;
        const int k0 = kb * GROUP;
        #pragma unroll
        for (int i = 0; i < 7; i++) {
            int c = tid + i * 256;          // 1632 chunks of 16B
            if (c < 512) {                  // A: 128 rows x 4 chunks
                int row = c >> 2, ch = (c & 3) << 4;
                cp_async16(st + A_OFF + row * BROW + ch,
                           &g_Aq[(size_t)(m0 + row) * K_IN + k0 + ch]);
            } else if (c < 1536) {          // B: 256 rows x 4 chunks
                int cb = c - 512;
                int row = cb >> 2, ch = (cb & 3) << 4;
                cp_async16(st + B_OFF + row * BROW + ch,
                           &g_Wq[(size_t)(n0 + row) * K_IN + k0 + ch]);
            } else if (c < 1568) {          // ascale: 128 floats
                int i4 = c - 1536;
                cp_async16(st + ASC_OFF + i4 * 16, &g_AS[(size_t)kb * M_TOK + m0 + i4 * 4]);
            } else if (c < 1632) {          // wscale: 256 floats
                int i4 = c - 1568;
                cp_async16(st + WSC_OFF + i4 * 16, &wsc[(size_t)kb * N_OUT + n0 + i4 * 4]);
            }
        }
        asm volatile("cp.async.commit_group;");
    };

    float accf[4][8][4];
    #pragma unroll
    for (int mi = 0; mi < 4; mi++)
        #pragma unroll
        for (int ni = 0; ni < 8; ni++)
            #pragma unroll
            for (int q = 0; q < 4; q++) accf[mi][ni][q] = 0.0f;

    load_stage(0, 0);
    load_stage(1, 1);
    load_stage(2, 2);

    for (int kt = 0; kt < KT; kt++) {
        asm volatile("cp.async.wait_group 2;");
        __syncthreads();
        int kb_next = kt + 3;
        load_stage((kt + 3) & 3, kb_next < KT ? kb_next : 0);

        const uint32_t st = sbase + (kt & 3) * ST_STRIDE;
        const float* ascp = (const float*)(smem + (kt & 3) * ST_STRIDE + ASC_OFF);
        const float* wscp = (const float*)(smem + (kt & 3) * ST_STRIDE + WSC_OFF);

        // scales for this group
        float sa[4][2], sw[8][2];
        #pragma unroll
        for (int mi = 0; mi < 4; mi++) {
            int r = wm + mi * 16 + (lane >> 2);
            sa[mi][0] = ascp[r];
            sa[mi][1] = ascp[r + 8];
        }
        #pragma unroll
        for (int ni = 0; ni < 8; ni++) {
            int cidx = wn + ni * 8 + ((lane & 3) << 1);
            sw[ni][0] = wscp[cidx];
            sw[ni][1] = wscp[cidx + 1];
        }

        // fragments (int8): a[mi][ks][4], b[nj][ks][4]
        uint32_t a[4][2][4], b[4][2][4];
        #pragma unroll
        for (int ks = 0; ks < 2; ks++) {
            #pragma unroll
            for (int mi = 0; mi < 4; mi++) {
                int row = wm + mi * 16 + (lane & 15);
                uint32_t addr = st + A_OFF + row * BROW + ks * 32 + ((lane >> 4) << 4);
                ldmx4(addr, a[mi][ks][0], a[mi][ks][1], a[mi][ks][2], a[mi][ks][3]);
            }
            #pragma unroll
            for (int nj = 0; nj < 4; nj++) {
                int row = wn + nj * 16 + (lane & 7) + ((lane >> 4) << 3);
                uint32_t addr = st + B_OFF + row * BROW + ks * 32 + (((lane >> 3) & 1) << 4);
                ldmx4(addr, b[nj][ks][0], b[nj][ks][1], b[nj][ks][2], b[nj][ks][3]);
            }
        }

        #pragma unroll
        for (int mi = 0; mi < 4; mi++) {
            #pragma unroll
            for (int ni = 0; ni < 8; ni++) {
                int c[4] = {0, 0, 0, 0};
                const int nj = ni >> 1, h = (ni & 1) * 2;
                imma16832(c, a[mi][0][0], a[mi][0][1], a[mi][0][2], a[mi][0][3],
                          b[nj][0][h], b[nj][0][h + 1]);
                imma16832(c, a[mi][1][0], a[mi][1][1], a[mi][1][2], a[mi][1][3],
                          b[nj][1][h], b[nj][1][h + 1]);
                accf[mi][ni][0] = fmaf(__int2float_rn(c[0]), sa[mi][0] * sw[ni][0], accf[mi][ni][0]);
                accf[mi][ni][1] = fmaf(__int2float_rn(c[1]), sa[mi][0] * sw[ni][1], accf[mi][ni][1]);
                accf[mi][ni][2] = fmaf(__int2float_rn(c[2]), sa[mi][1] * sw[ni][0], accf[mi][ni][2]);
                accf[mi][ni][3] = fmaf(__int2float_rn(c[3]), sa[mi][1] * sw[ni][1], accf[mi][ni][3]);
            }
        }
    }

    // ---- lora via fp16 HMMA: 2 k-steps of rank-32 ----
    asm volatile("cp.async.wait_group 0;");
    __syncthreads();
    // load la[128][32]h, lu[256][32]h into stage-0 region (stride 80B)
    {
        #pragma unroll
        for (int i = 0; i < 6; i++) {
            int c = tid + i * 256;          // 1536 chunks
            if (c < 512) {
                int row = c >> 2, ch = (c & 3) << 4;
                cp_async16(sbase + A_OFF + row * BROW + ch,
                           &g_LAh[(size_t)(m0 + row) * RANK + (ch >> 1)]);
            } else {
                int cb = c - 512;
                int row = cb >> 2, ch = (cb & 3) << 4;
                cp_async16(sbase + B_OFF + row * BROW + ch,
                           &g_LUh[(size_t)(n0 + row) * RANK + (ch >> 1)]);
            }
        }
        asm volatile("cp.async.commit_group;");
        asm volatile("cp.async.wait_group 0;");
        __syncthreads();

        #pragma unroll
        for (int ks = 0; ks < 2; ks++) {
            const int kq = ks * 16;         // halves
            uint32_t a[4][4];
            #pragma unroll
            for (int mi = 0; mi < 4; mi++) {
                int row = wm + mi * 16 + (lane & 15);
                int col = kq + ((lane >> 4) << 3);
                ldmx4(sbase + A_OFF + row * BROW + col * 2,
                      a[mi][0], a[mi][1], a[mi][2], a[mi][3]);
            }
            uint32_t b[4][4];
            #pragma unroll
            for (int nj = 0; nj < 4; nj++) {
                int row = wn + nj * 16 + (lane & 7) + ((lane >> 4) << 3);
                int col = kq + (((lane >> 3) & 1) << 3);
                ldmx4(sbase + B_OFF + row * BROW + col * 2,
                      b[nj][0], b[nj][1], b[nj][2], b[nj][3]);
            }
            #pragma unroll
            for (int mi = 0; mi < 4; mi++)
                #pragma unroll
                for (int ni = 0; ni < 8; ni++)
                    hmma16816(accf[mi][ni],
                              a[mi][0], a[mi][1], a[mi][2], a[mi][3],
                              b[ni >> 1][(ni & 1) * 2 + 0],
                              b[ni >> 1][(ni & 1) * 2 + 1]);
        }
    }

    // epilogue: + bias, fp32 stores
    #pragma unroll
    for (int ni = 0; ni < 8; ni++) {
        int gn = n0 + wn + ni * 8 + ((lane & 3) << 1);
        float b0 = __ldg(&bias[gn]);
        float b1 = __ldg(&bias[gn + 1]);
        #pragma unroll
        for (int mi = 0; mi < 4; mi++) {
            int gm = m0 + wm + mi * 16 + (lane >> 2);
            float2 v0 = make_float2(accf[mi][ni][0] + b0, accf[mi][ni][1] + b1);
            float2 v1 = make_float2(accf[mi][ni][2] + b0, accf[mi][ni][3] + b1);
            *reinterpret_cast<float2*>(&out[(size_t)gm * N_OUT + gn]) = v0;
            *reinterpret_cast<float2*>(&out[(size_t)(gm + 8) * N_OUT + gn]) = v1;
        }
    }
}

// ---------------- K3: RMSNorm + RoPE on Q and K sections, in place ----------------
__global__ void norm_rope_kernel(float* __restrict__ out,
                                 const float* __restrict__ nq,
                                 const float* __restrict__ nk,
                                 const float* __restrict__ rot) {
    int m   = blockIdx.x;
    int h   = blockIdx.y;            // 0..47
    int sec = (h >= N_HEADS) ? 1 : 0;
    int head = h - sec * N_HEADS;
    int d   = threadIdx.x;           // 0..127
    size_t base = (size_t)m * N_OUT + (size_t)sec * (N_HEADS * HEAD_DIM)
                + (size_t)head * HEAD_DIM;

    float t  = out[base + d];
    float ss = t * t;
    #pragma unroll
    for (int o = 16; o > 0; o >>= 1) ss += __shfl_xor_sync(0xffffffffu, ss, o);

    __shared__ float ws[4];
    __shared__ float sm[HEAD_DIM];
    if ((d & 31) == 0) ws[d >> 5] = ss;
    __syncthreads();
    float tot = ws[0] + ws[1] + ws[2] + ws[3];
    float rn  = rsqrtf(tot * (1.0f / 128.0f) + 1e-6f);
    float g   = sec ? nk[d] : nq[d];
    sm[d] = t * rn * g;
    __syncthreads();

    if (d < 64) {
        float e = sm[2 * d], o2 = sm[2 * d + 1];
        float c = rot[(size_t)m * 128 + 2 * d];
        float s = rot[(size_t)m * 128 + 2 * d + 1];
        out[base + 2 * d]     = e * c - o2 * s;
        out[base + 2 * d + 1] = e * s + o2 * c;
    }
}

// ---------------- launch ----------------
extern "C" void kernel_launch(void* const* d_in, const int* in_sizes, int n_in,
                              void* d_out, int out_size) {
    const float*  x      = (const float*)d_in[0];
    const void*   qw     = d_in[1];
    const float*  wsc    = (const float*)d_in[2];
    const float*  bias   = (const float*)d_in[3];
    const float*  ldn    = (const float*)d_in[4];
    const float*  lup    = (const float*)d_in[5];
    const float*  smooth = (const float*)d_in[6];
    const float*  nq     = (const float*)d_in[7];
    const float*  nk     = (const float*)d_in[8];
    const float*  rot    = (const float*)d_in[9];
    float* out = (float*)d_out;

    detect_qw_kernel<<<1, 256>>>((const int*)qw);

    {
        int tot = N_OUT * (K_IN / 2);
        unpack_w_kernel<<<(tot + 255) / 256, 256>>>(qw);
        lora_wh_kernel<<<N_OUT, RANK>>>(lup);
    }
    quant_act_kernel<<<M_TOK, 256>>>(x, smooth, ldn);

    cudaFuncSetAttribute(gemm_kernel,
                         cudaFuncAttributeMaxDynamicSharedMemorySize, SMEM_TOTAL);
    {
        dim3 grid(N_OUT / BN, M_TOK / BM);   // (36, 32)
        gemm_kernel<<<grid, 256, SMEM_TOTAL>>>(out, bias, wsc);
    }
    {
        dim3 grid(M_TOK, 2 * N_HEADS);
        norm_rope_kernel<<<grid, 128>>>(out, nq, nk, rot);
    }
}

// round 14
// speedup vs baseline: 1.2838x; 1.2838x over previous
#include <cuda_runtime.h>
#include <cuda_fp16.h>
#include <cuda_fp8.h>
#include <cstdint>

// Problem constants
#define M_TOK   4096
#define K_IN    3072
#define N_OUT   9216
#define GROUP   64
#define RANK    32
#define NGRP    48            // K_IN / GROUP
#define HEAD_DIM 128
#define N_HEADS 24

// ---------------- scratch (device globals: allocation-free) ----------------
__device__ uint8_t g_Aq[(size_t)M_TOK * K_IN];   // activations as e4m3 (exact ints -8..7)
__device__ uint8_t g_Wq[(size_t)N_OUT * K_IN];   // weights as e4m3 (exact ints -8..7)
__device__ float   g_AS[(size_t)NGRP * M_TOK];   // act scales, transposed [g][m]
__device__ __half  g_LAh[(size_t)M_TOK * RANK];  // lora_act fp16
__device__ __half  g_LUh[(size_t)N_OUT * RANK];  // lora_up fp16
__device__ int     g_qw_is_i32;

__device__ __forceinline__ uint8_t f2e4m3(float f) {
    __nv_fp8_e4m3 v(f);
    return *reinterpret_cast<uint8_t*>(&v);
}

// ---------------- detect qweight storage dtype ----------------
__global__ void detect_qw_kernel(const int* __restrict__ qw32) {
    int ok = 1;
    for (int i = threadIdx.x; i < 8192; i += 256) {
        int hi = qw32[i] >> 8;
        if (hi != 0 && hi != -1) ok = 0;
    }
    __syncthreads();
    unsigned all = __all_sync(0xffffffffu, ok);
    __shared__ int wall[8];
    if ((threadIdx.x & 31) == 0) wall[threadIdx.x >> 5] = (int)all;
    __syncthreads();
    if (threadIdx.x == 0) {
        int r = 1;
        #pragma unroll
        for (int i = 0; i < 8; i++) r &= wall[i];
        g_qw_is_i32 = r;
    }
}

// ---------------- K0: weight nibble unpack -> e4m3 ----------------
__global__ void unpack_w_kernel(const void* __restrict__ qw_raw) {
    int idx = blockIdx.x * 256 + threadIdx.x;
    const int TOT = N_OUT * (K_IN / 2);
    if (idx >= TOT) return;
    int b;
    if (g_qw_is_i32) b = ((const int*)qw_raw)[idx];
    else             b = ((const int8_t*)qw_raw)[idx];
    int lo = ((b & 0xF) ^ 8) - 8;
    int hi = (b << 24) >> 28;
    uchar2 v;
    v.x = f2e4m3((float)lo);
    v.y = f2e4m3((float)hi);
    *reinterpret_cast<uchar2*>(&g_Wq[(size_t)idx * 2]) = v;
}

__global__ void lora_wh_kernel(const float* __restrict__ lup) {
    int n = blockIdx.x;
    int t = threadIdx.x;   // 0..31
    g_LUh[n * RANK + t] = __float2half(lup[n * RANK + t]);
}

// ---------------- K1: activation quant (e4m3 + scales) + lora_act ----------------
__global__ void quant_act_kernel(const float* __restrict__ x,
                                 const float* __restrict__ smooth,
                                 const float* __restrict__ ldn) {
    __shared__ float xs[K_IN];
    __shared__ float part[8][RANK];
    int m    = blockIdx.x;
    int tid  = threadIdx.x;
    int lane = tid & 31;
    int w    = tid >> 5;

    const float* xr = x + (size_t)m * K_IN;
    for (int i = tid; i < K_IN; i += 256)
        xs[i] = __fdiv_rn(xr[i], smooth[i]);
    __syncthreads();

    #pragma unroll
    for (int j = 0; j < 6; j++) {
        int g  = w + 8 * j;
        int k1 = g * GROUP + lane;
        float v1 = xs[k1], v2 = xs[k1 + 32];
        float amax = fmaxf(fabsf(v1), fabsf(v2));
        #pragma unroll
        for (int o = 16; o > 0; o >>= 1)
            amax = fmaxf(amax, __shfl_xor_sync(0xffffffffu, amax, o));
        float ascale = fmaxf(__fdiv_rn(amax, 7.0f), 1e-8f);
        float q1 = fminf(fmaxf(rintf(__fdiv_rn(v1, ascale)), -8.0f), 7.0f);
        float q2 = fminf(fmaxf(rintf(__fdiv_rn(v2, ascale)), -8.0f), 7.0f);
        g_Aq[(size_t)m * K_IN + k1]      = f2e4m3(q1);
        g_Aq[(size_t)m * K_IN + k1 + 32] = f2e4m3(q2);
        if (lane == 0) g_AS[(size_t)g * M_TOK + m] = ascale;
    }

    float acc = 0.0f;
    int kbeg = w * (K_IN / 8), kend = kbeg + (K_IN / 8);
    for (int k = kbeg; k < kend; k++)
        acc = fmaf(xs[k], ldn[k * RANK + lane], acc);
    part[w][lane] = acc;
    __syncthreads();
    if (w == 0) {
        float s = 0.0f;
        #pragma unroll
        for (int i = 0; i < 8; i++) s += part[i][lane];
        g_LAh[m * RANK + lane] = __float2half(s);
    }
}

// ---------------- K2: fp8 e4m3 GEMM 128x256 (512 thr), group fixup, lora HMMA ----------------
#define BM 128
#define BN 256
#define BROW 80               // padded row stride bytes
#define NSTAGE 4
#define KT NGRP               // 48
#define NTHREADS 512
// per-stage layout (bytes)
#define A_OFF   0
#define B_OFF   (BM * BROW)               // 10240
#define ASC_OFF (B_OFF + BN * BROW)       // 30720
#define WSC_OFF (ASC_OFF + BM * 4)        // 31232
#define ST_STRIDE (WSC_OFF + BN * 4 - ASC_OFF + ASC_OFF)  // 32256
#define SMEM_TOTAL (NSTAGE * ST_STRIDE)   // 129024

__device__ __forceinline__ void cp_async16(uint32_t dst, const void* src) {
    asm volatile("cp.async.cg.shared.global [%0], [%1], 16;" :: "r"(dst), "l"(src));
}
__device__ __forceinline__ void ldmx4(uint32_t addr, uint32_t& r0, uint32_t& r1,
                                      uint32_t& r2, uint32_t& r3) {
    asm volatile("ldmatrix.sync.aligned.m8n8.x4.shared.b16 {%0,%1,%2,%3}, [%4];"
                 : "=r"(r0), "=r"(r1), "=r"(r2), "=r"(r3) : "r"(addr));
}
__device__ __forceinline__ void fmma8(float* c, uint32_t a0, uint32_t a1,
                                      uint32_t a2, uint32_t a3,
                                      uint32_t b0, uint32_t b1) {
    asm volatile("mma.sync.aligned.m16n8k32.row.col.f32.e4m3.e4m3.f32 "
                 "{%0,%1,%2,%3}, {%4,%5,%6,%7}, {%8,%9}, {%0,%1,%2,%3};"
                 : "+f"(c[0]), "+f"(c[1]), "+f"(c[2]), "+f"(c[3])
                 : "r"(a0), "r"(a1), "r"(a2), "r"(a3), "r"(b0), "r"(b1));
}
__device__ __forceinline__ void hmma16816(float* c, uint32_t a0, uint32_t a1,
                                          uint32_t a2, uint32_t a3,
                                          uint32_t b0, uint32_t b1) {
    asm volatile("mma.sync.aligned.m16n8k16.row.col.f32.f16.f16.f32 "
                 "{%0,%1,%2,%3}, {%4,%5,%6,%7}, {%8,%9}, {%0,%1,%2,%3};"
                 : "+f"(c[0]), "+f"(c[1]), "+f"(c[2]), "+f"(c[3])
                 : "r"(a0), "r"(a1), "r"(a2), "r"(a3), "r"(b0), "r"(b1));
}

__global__ void __launch_bounds__(NTHREADS, 1)
gemm_kernel(float* __restrict__ out, const float* __restrict__ bias,
            const float* __restrict__ wsc) {
    extern __shared__ char smem[];
    uint32_t sbase;
    asm("{ .reg .u64 t; cvta.to.shared.u64 t, %1; cvt.u32.u64 %0, t; }"
        : "=r"(sbase) : "l"(smem));

    const int tid  = threadIdx.x;
    const int lane = tid & 31;
    const int w    = tid >> 5;          // 0..15
    const int wm   = (w >> 2) * 32;     // 4 warps in m, 32 rows each
    const int wn   = (w & 3) * 64;      // 4 warps in n, 64 cols each
    const int m0   = blockIdx.y * BM;
    const int n0   = blockIdx.x * BN;

    auto load_stage = [&](int s, int kb) {
        const uint32_t st = sbase + s * ST_STRIDE;
        const int k0 = kb * GROUP;
        #pragma unroll
        for (int i = 0; i < 4; i++) {
            int c = tid + i * NTHREADS;     // 2048 slots, 1632 used
            if (c < 512) {                  // A: 128 rows x 4 chunks
                int row = c >> 2, ch = (c & 3) << 4;
                cp_async16(st + A_OFF + row * BROW + ch,
                           &g_Aq[(size_t)(m0 + row) * K_IN + k0 + ch]);
            } else if (c < 1536) {          // B: 256 rows x 4 chunks
                int cb = c - 512;
                int row = cb >> 2, ch = (cb & 3) << 4;
                cp_async16(st + B_OFF + row * BROW + ch,
                           &g_Wq[(size_t)(n0 + row) * K_IN + k0 + ch]);
            } else if (c < 1568) {          // ascale: 128 floats
                int i4 = c - 1536;
                cp_async16(st + ASC_OFF + i4 * 16, &g_AS[(size_t)kb * M_TOK + m0 + i4 * 4]);
            } else if (c < 1632) {          // wscale: 256 floats
                int i4 = c - 1568;
                cp_async16(st + WSC_OFF + i4 * 16, &wsc[(size_t)kb * N_OUT + n0 + i4 * 4]);
            }
        }
        asm volatile("cp.async.commit_group;");
    };

    float accf[2][8][4];
    #pragma unroll
    for (int mi = 0; mi < 2; mi++)
        #pragma unroll
        for (int ni = 0; ni < 8; ni++)
            #pragma unroll
            for (int q = 0; q < 4; q++) accf[mi][ni][q] = 0.0f;

    load_stage(0, 0);
    load_stage(1, 1);
    load_stage(2, 2);

    for (int kt = 0; kt < KT; kt++) {
        asm volatile("cp.async.wait_group 2;");
        __syncthreads();
        int kb_next = kt + 3;
        load_stage((kt + 3) & 3, kb_next < KT ? kb_next : 0);

        const uint32_t st = sbase + (kt & 3) * ST_STRIDE;
        const float* ascp = (const float*)(smem + (kt & 3) * ST_STRIDE + ASC_OFF);
        const float* wscp = (const float*)(smem + (kt & 3) * ST_STRIDE + WSC_OFF);

        // scales for this group
        float sa[2][2], sw[8][2];
        #pragma unroll
        for (int mi = 0; mi < 2; mi++) {
            int r = wm + mi * 16 + (lane >> 2);
            sa[mi][0] = ascp[r];
            sa[mi][1] = ascp[r + 8];
        }
        #pragma unroll
        for (int ni = 0; ni < 8; ni++) {
            int cidx = wn + ni * 8 + ((lane & 3) << 1);
            sw[ni][0] = wscp[cidx];
            sw[ni][1] = wscp[cidx + 1];
        }

        // fragments (e4m3): byte layout identical to verified s8-k32 mapping
        uint32_t a[2][2][4], b[4][2][4];
        #pragma unroll
        for (int ks = 0; ks < 2; ks++) {
            #pragma unroll
            for (int mi = 0; mi < 2; mi++) {
                int row = wm + mi * 16 + (lane & 15);
                uint32_t addr = st + A_OFF + row * BROW + ks * 32 + ((lane >> 4) << 4);
                ldmx4(addr, a[mi][ks][0], a[mi][ks][1], a[mi][ks][2], a[mi][ks][3]);
            }
            #pragma unroll
            for (int nj = 0; nj < 4; nj++) {
                int row = wn + nj * 16 + (lane & 7) + ((lane >> 4) << 3);
                uint32_t addr = st + B_OFF + row * BROW + ks * 32 + (((lane >> 3) & 1) << 4);
                ldmx4(addr, b[nj][ks][0], b[nj][ks][1], b[nj][ks][2], b[nj][ks][3]);
            }
        }

        #pragma unroll
        for (int mi = 0; mi < 2; mi++) {
            #pragma unroll
            for (int ni = 0; ni < 8; ni++) {
                float c[4] = {0.0f, 0.0f, 0.0f, 0.0f};
                const int nj = ni >> 1, h = (ni & 1) * 2;
                fmma8(c, a[mi][0][0], a[mi][0][1], a[mi][0][2], a[mi][0][3],
                      b[nj][0][h], b[nj][0][h + 1]);
                fmma8(c, a[mi][1][0], a[mi][1][1], a[mi][1][2], a[mi][1][3],
                      b[nj][1][h], b[nj][1][h + 1]);
                accf[mi][ni][0] = fmaf(c[0], sa[mi][0] * sw[ni][0], accf[mi][ni][0]);
                accf[mi][ni][1] = fmaf(c[1], sa[mi][0] * sw[ni][1], accf[mi][ni][1]);
                accf[mi][ni][2] = fmaf(c[2], sa[mi][1] * sw[ni][0], accf[mi][ni][2]);
                accf[mi][ni][3] = fmaf(c[3], sa[mi][1] * sw[ni][1], accf[mi][ni][3]);
            }
        }
    }

    // ---- lora via fp16 HMMA: 2 k-steps of rank-32 ----
    asm volatile("cp.async.wait_group 0;");
    __syncthreads();
    {
        #pragma unroll
        for (int i = 0; i < 3; i++) {
            int c = tid + i * NTHREADS;     // 1536 chunks
            if (c < 512) {
                int row = c >> 2, ch = (c & 3) << 4;
                cp_async16(sbase + A_OFF + row * BROW + ch,
                           &g_LAh[(size_t)(m0 + row) * RANK + (ch >> 1)]);
            } else if (c < 1536) {
                int cb = c - 512;
                int row = cb >> 2, ch = (cb & 3) << 4;
                cp_async16(sbase + B_OFF + row * BROW + ch,
                           &g_LUh[(size_t)(n0 + row) * RANK + (ch >> 1)]);
            }
        }
        asm volatile("cp.async.commit_group;");
        asm volatile("cp.async.wait_group 0;");
        __syncthreads();

        #pragma unroll
        for (int ks = 0; ks < 2; ks++) {
            const int kq = ks * 16;         // halves
            uint32_t a[2][4];
            #pragma unroll
            for (int mi = 0; mi < 2; mi++) {
                int row = wm + mi * 16 + (lane & 15);
                int col = kq + ((lane >> 4) << 3);
                ldmx4(sbase + A_OFF + row * BROW + col * 2,
                      a[mi][0], a[mi][1], a[mi][2], a[mi][3]);
            }
            uint32_t b[4][4];
            #pragma unroll
            for (int nj = 0; nj < 4; nj++) {
                int row = wn + nj * 16 + (lane & 7) + ((lane >> 4) << 3);
                int col = kq + (((lane >> 3) & 1) << 3);
                ldmx4(sbase + B_OFF + row * BROW + col * 2,
                      b[nj][0], b[nj][1], b[nj][2], b[nj][3]);
            }
            #pragma unroll
            for (int mi = 0; mi < 2; mi++)
                #pragma unroll
                for (int ni = 0; ni < 8; ni++)
                    hmma16816(accf[mi][ni],
                              a[mi][0], a[mi][1], a[mi][2], a[mi][3],
                              b[ni >> 1][(ni & 1) * 2 + 0],
                              b[ni >> 1][(ni & 1) * 2 + 1]);
        }
    }

    // epilogue: + bias, fp32 stores
    #pragma unroll
    for (int ni = 0; ni < 8; ni++) {
        int gn = n0 + wn + ni * 8 + ((lane & 3) << 1);
        float b0 = __ldg(&bias[gn]);
        float b1 = __ldg(&bias[gn + 1]);
        #pragma unroll
        for (int mi = 0; mi < 2; mi++) {
            int gm = m0 + wm + mi * 16 + (lane >> 2);
            float2 v0 = make_float2(accf[mi][ni][0] + b0, accf[mi][ni][1] + b1);
            float2 v1 = make_float2(accf[mi][ni][2] + b0, accf[mi][ni][3] + b1);
            *reinterpret_cast<float2*>(&out[(size_t)gm * N_OUT + gn]) = v0;
            *reinterpret_cast<float2*>(&out[(size_t)(gm + 8) * N_OUT + gn]) = v1;
        }
    }
}

// ---------------- K3: RMSNorm + RoPE on Q and K sections, in place ----------------
__global__ void norm_rope_kernel(float* __restrict__ out,
                                 const float* __restrict__ nq,
                                 const float* __restrict__ nk,
                                 const float* __restrict__ rot) {
    int m   = blockIdx.x;
    int h   = blockIdx.y;            // 0..47
    int sec = (h >= N_HEADS) ? 1 : 0;
    int head = h - sec * N_HEADS;
    int d   = threadIdx.x;           // 0..127
    size_t base = (size_t)m * N_OUT + (size_t)sec * (N_HEADS * HEAD_DIM)
                + (size_t)head * HEAD_DIM;

    float t  = out[base + d];
    float ss = t * t;
    #pragma unroll
    for (int o = 16; o > 0; o >>= 1) ss += __shfl_xor_sync(0xffffffffu, ss, o);

    __shared__ float ws[4];
    __shared__ float sm[HEAD_DIM];
    if ((d & 31) == 0) ws[d >> 5] = ss;
    __syncthreads();
    float tot = ws[0] + ws[1] + ws[2] + ws[3];
    float rn  = rsqrtf(tot * (1.0f / 128.0f) + 1e-6f);
    float g   = sec ? nk[d] : nq[d];
    sm[d] = t * rn * g;
    __syncthreads();

    if (d < 64) {
        float e = sm[2 * d], o2 = sm[2 * d + 1];
        float c = rot[(size_t)m * 128 + 2 * d];
        float s = rot[(size_t)m * 128 + 2 * d + 1];
        out[base + 2 * d]     = e * c - o2 * s;
        out[base + 2 * d + 1] = e * s + o2 * c;
    }
}

// ---------------- launch ----------------
extern "C" void kernel_launch(void* const* d_in, const int* in_sizes, int n_in,
                              void* d_out, int out_size) {
    const float*  x      = (const float*)d_in[0];
    const void*   qw     = d_in[1];
    const float*  wsc    = (const float*)d_in[2];
    const float*  bias   = (const float*)d_in[3];
    const float*  ldn    = (const float*)d_in[4];
    const float*  lup    = (const float*)d_in[5];
    const float*  smooth = (const float*)d_in[6];
    const float*  nq     = (const float*)d_in[7];
    const float*  nk     = (const float*)d_in[8];
    const float*  rot    = (const float*)d_in[9];
    float* out = (float*)d_out;

    detect_qw_kernel<<<1, 256>>>((const int*)qw);

    {
        int tot = N_OUT * (K_IN / 2);
        unpack_w_kernel<<<(tot + 255) / 256, 256>>>(qw);
        lora_wh_kernel<<<N_OUT, RANK>>>(lup);
    }
    quant_act_kernel<<<M_TOK, 256>>>(x, smooth, ldn);

    cudaFuncSetAttribute(gemm_kernel,
                         cudaFuncAttributeMaxDynamicSharedMemorySize, SMEM_TOTAL);
    {
        dim3 grid(N_OUT / BN, M_TOK / BM);   // (36, 32)
        gemm_kernel<<<grid, NTHREADS, SMEM_TOTAL>>>(out, bias, wsc);
    }
    {
        dim3 grid(M_TOK, 2 * N_HEADS);
        norm_rope_kernel<<<grid, 128>>>(out, nq, nk, rot);
    }
}

// round 16
// speedup vs baseline: 2.2012x; 1.7146x over previous
#include <cuda_runtime.h>
#include <cuda_fp16.h>
#include <cstdint>

// Problem constants
#define M_TOK   4096
#define K_IN    3072
#define N_OUT   9216
#define GROUP   64
#define RANK    32
#define KE      3104          // 3072 + 32 (lora), multiple of 32
#define HEAD_DIM 128
#define N_HEADS 24

// ---------------- scratch (device globals: allocation-free) ----------------
__device__ __half g_A[(size_t)M_TOK * KE];   // dequantized activations + lora_act
__device__ __half g_W[(size_t)N_OUT * KE];   // dequantized weights + lora_up
__device__ int    g_qw_is_i32;

// ---------------- detect qweight storage dtype ----------------
__global__ void detect_qw_kernel(const int* __restrict__ qw32) {
    int ok = 1;
    for (int i = threadIdx.x; i < 8192; i += 256) {
        int hi = qw32[i] >> 8;
        if (hi != 0 && hi != -1) ok = 0;
    }
    __syncthreads();
    unsigned all = __all_sync(0xffffffffu, ok);
    __shared__ int wall[8];
    if ((threadIdx.x & 31) == 0) wall[threadIdx.x >> 5] = (int)all;
    __syncthreads();
    if (threadIdx.x == 0) {
        int r = 1;
        #pragma unroll
        for (int i = 0; i < 8; i++) r &= wall[i];
        g_qw_is_i32 = r;
    }
}

// ---------------- K0: weight dequant -> fp16 ----------------
__global__ void dequant_w_kernel(const void* __restrict__ qw_raw,
                                 const float* __restrict__ wsc) {
    int idx = blockIdx.x * 256 + threadIdx.x;
    const int TOT = N_OUT * (K_IN / 2);
    if (idx >= TOT) return;
    int n  = idx / (K_IN / 2);
    int jp = idx - n * (K_IN / 2);
    int k  = jp * 2;
    float s = wsc[(k >> 6) * N_OUT + n];
    int b;
    if (g_qw_is_i32) b = ((const int*)qw_raw)[idx];
    else             b = ((const int8_t*)qw_raw)[idx];
    int lo = ((b & 0xF) ^ 8) - 8;
    int hi = (b << 24) >> 28;
    __half2 hv = __floats2half2_rn((float)lo * s, (float)hi * s);
    *reinterpret_cast<__half2*>(&g_W[(size_t)n * KE + k]) = hv;
}

// append lora_up (cols 3072..3103)
__global__ void lora_w_kernel(const float* __restrict__ lup) {
    int n = blockIdx.x;
    int t = threadIdx.x;   // 0..31
    g_W[(size_t)n * KE + K_IN + t] = __float2half(lup[n * RANK + t]);
}

// ---------------- K1: activation quant + lora_act, 4 tokens/block ----------------
#define TOK4 4
#define QA_SMEM (TOK4 * K_IN * 4 + 8 * TOK4 * RANK * 4)   // 49152 + 4096 = 53248

__global__ void __launch_bounds__(256)
quant_act_kernel(const float* __restrict__ x,
                 const float* __restrict__ smooth,
                 const float* __restrict__ ldn) {
    extern __shared__ float qs[];
    float* xs   = qs;                       // [TOK4][K_IN]
    float* part = qs + TOK4 * K_IN;         // [8][TOK4][RANK]
    const int mb   = blockIdx.x * TOK4;
    const int tid  = threadIdx.x;
    const int lane = tid & 31;
    const int w    = tid >> 5;

    // load 4 tokens, divide by smooth (IEEE rn, matches reference)
    for (int i = tid; i < K_IN / 4; i += 256) {
        float4 sm4 = reinterpret_cast<const float4*>(smooth)[i];
        #pragma unroll
        for (int t = 0; t < TOK4; t++) {
            float4 v = reinterpret_cast<const float4*>(x + (size_t)(mb + t) * K_IN)[i];
            xs[t * K_IN + i * 4 + 0] = __fdiv_rn(v.x, sm4.x);
            xs[t * K_IN + i * 4 + 1] = __fdiv_rn(v.y, sm4.y);
            xs[t * K_IN + i * 4 + 2] = __fdiv_rn(v.z, sm4.z);
            xs[t * K_IN + i * 4 + 3] = __fdiv_rn(v.w, sm4.w);
        }
    }
    __syncthreads();

    // group quantization: 8 warps x 6 groups x 4 tokens
    #pragma unroll
    for (int j = 0; j < 6; j++) {
        int g  = w + 8 * j;
        int k1 = g * GROUP + lane;
        #pragma unroll
        for (int t = 0; t < TOK4; t++) {
            float v1 = xs[t * K_IN + k1], v2 = xs[t * K_IN + k1 + 32];
            float amax = fmaxf(fabsf(v1), fabsf(v2));
            #pragma unroll
            for (int o = 16; o > 0; o >>= 1)
                amax = fmaxf(amax, __shfl_xor_sync(0xffffffffu, amax, o));
            float ascale = fmaxf(__fdiv_rn(amax, 7.0f), 1e-8f);
            float q1 = fminf(fmaxf(rintf(__fdiv_rn(v1, ascale)), -8.0f), 7.0f);
            float q2 = fminf(fmaxf(rintf(__fdiv_rn(v2, ascale)), -8.0f), 7.0f);
            g_A[(size_t)(mb + t) * KE + k1]      = __float2half(q1 * ascale);
            g_A[(size_t)(mb + t) * KE + k1 + 32] = __float2half(q2 * ascale);
        }
    }

    // lora_act: acc[t] = sum_k xs[t][k] * ldn[k][lane], ldn read once per block
    float acc[TOK4] = {0.0f, 0.0f, 0.0f, 0.0f};
    int kbeg = w * (K_IN / 8), kend = kbeg + (K_IN / 8);
    for (int k = kbeg; k < kend; k++) {
        float l = ldn[k * RANK + lane];
        #pragma unroll
        for (int t = 0; t < TOK4; t++)
            acc[t] = fmaf(xs[t * K_IN + k], l, acc[t]);
    }
    #pragma unroll
    for (int t = 0; t < TOK4; t++)
        part[(w * TOK4 + t) * RANK + lane] = acc[t];
    __syncthreads();
    if (w < TOK4) {      // warp w reduces token w
        float s = 0.0f;
        #pragma unroll
        for (int i = 0; i < 8; i++) s += part[(i * TOK4 + w) * RANK + lane];
        g_A[(size_t)(mb + w) * KE + K_IN + lane] = __float2half(s);
    }
}

// ---------------- K2: fp16 GEMM 128x256, 4-stage, fused bias+RMSNorm+RoPE ----------------
#define BM 128
#define BN 256
#define BK 32
#define BKP 40            // padded row stride (halves)
#define KT (KE / BK)      // 97
#define ST_A_OFF   0
#define ST_B_OFF   (BM * BKP * 2)                 // 10240
#define ST_STRIDE  ((BM + BN) * BKP * 2)          // 30720
#define SMEM_TOTAL (4 * ST_STRIDE)                // 122880

__device__ __forceinline__ void cp_async16(uint32_t dst, const void* src) {
    asm volatile("cp.async.cg.shared.global [%0], [%1], 16;" :: "r"(dst), "l"(src));
}
__device__ __forceinline__ void ldmx4(uint32_t addr, uint32_t& r0, uint32_t& r1,
                                      uint32_t& r2, uint32_t& r3) {
    asm volatile("ldmatrix.sync.aligned.m8n8.x4.shared.b16 {%0,%1,%2,%3}, [%4];"
                 : "=r"(r0), "=r"(r1), "=r"(r2), "=r"(r3) : "r"(addr));
}
__device__ __forceinline__ void mma16816(float* c, uint32_t a0, uint32_t a1,
                                         uint32_t a2, uint32_t a3,
                                         uint32_t b0, uint32_t b1) {
    asm volatile("mma.sync.aligned.m16n8k16.row.col.f32.f16.f16.f32 "
                 "{%0,%1,%2,%3}, {%4,%5,%6,%7}, {%8,%9}, {%0,%1,%2,%3};"
                 : "+f"(c[0]), "+f"(c[1]), "+f"(c[2]), "+f"(c[3])
                 : "r"(a0), "r"(a1), "r"(a2), "r"(a3), "r"(b0), "r"(b1));
}

__global__ void __launch_bounds__(256, 1)
gemm_kernel(float* __restrict__ out, const float* __restrict__ bias,
            const float* __restrict__ nq, const float* __restrict__ nk,
            const float* __restrict__ rot) {
    extern __shared__ char smem[];
    uint32_t sbase;
    asm("{ .reg .u64 t; cvta.to.shared.u64 t, %1; cvt.u32.u64 %0, t; }"
        : "=r"(sbase) : "l"(smem));

    const int tid  = threadIdx.x;
    const int lane = tid & 31;
    const int w    = tid >> 5;
    const int wm   = (w >> 2) * 64;    // 2 warps in m
    const int wn   = (w & 3) * 64;     // 4 warps in n
    const int m0   = blockIdx.y * BM;
    const int n0   = blockIdx.x * BN;

    auto load_stage = [&](int s, int kb) {
        const int k0 = kb * BK;
        const uint32_t st = sbase + s * ST_STRIDE;
        #pragma unroll
        for (int i = 0; i < 6; i++) {
            int c = tid + i * 256;     // 1536 chunks of 16B
            if (c < 512) {
                int row = c >> 2, col = (c & 3) << 3;
                cp_async16(st + ST_A_OFF + ((row * BKP + col) << 1),
                           &g_A[(size_t)(m0 + row) * KE + k0 + col]);
            } else {
                int cb = c - 512;
                int row = cb >> 2, col = (cb & 3) << 3;
                cp_async16(st + ST_B_OFF + ((row * BKP + col) << 1),
                           &g_W[(size_t)(n0 + row) * KE + k0 + col]);
            }
        }
        asm volatile("cp.async.commit_group;");
    };

    float acc[4][8][4];
    #pragma unroll
    for (int mi = 0; mi < 4; mi++)
        #pragma unroll
        for (int ni = 0; ni < 8; ni++)
            #pragma unroll
            for (int q = 0; q < 4; q++) acc[mi][ni][q] = 0.0f;

    load_stage(0, 0);
    load_stage(1, 1);
    load_stage(2, 2);

    for (int kt = 0; kt < KT; kt++) {
        asm volatile("cp.async.wait_group 2;");
        __syncthreads();
        int kb_next = kt + 3;
        load_stage((kt + 3) & 3, kb_next < KT ? kb_next : 0);

        const uint32_t st = sbase + (kt & 3) * ST_STRIDE;
        #pragma unroll
        for (int ks = 0; ks < 2; ks++) {
            const int kq = ks * 16;
            uint32_t a[4][4];
            #pragma unroll
            for (int mi = 0; mi < 4; mi++) {
                int row = wm + mi * 16 + (lane & 15);
                int col = kq + ((lane >> 4) << 3);
                ldmx4(st + ST_A_OFF + ((row * BKP + col) << 1),
                      a[mi][0], a[mi][1], a[mi][2], a[mi][3]);
            }
            uint32_t b[4][4];
            #pragma unroll
            for (int nj = 0; nj < 4; nj++) {
                int row = wn + nj * 16 + (lane & 7) + ((lane >> 4) << 3);
                int col = kq + (((lane >> 3) & 1) << 3);
                ldmx4(st + ST_B_OFF + ((row * BKP + col) << 1),
                      b[nj][0], b[nj][1], b[nj][2], b[nj][3]);
            }
            #pragma unroll
            for (int mi = 0; mi < 4; mi++)
                #pragma unroll
                for (int ni = 0; ni < 8; ni++)
                    mma16816(acc[mi][ni],
                             a[mi][0], a[mi][1], a[mi][2], a[mi][3],
                             b[ni >> 1][(ni & 1) * 2 + 0],
                             b[ni >> 1][(ni & 1) * 2 + 1]);
        }
        __syncthreads();
    }

    // ---------------- fused epilogue: bias (+ RMSNorm + RoPE for q/k) ----------------
    asm volatile("cp.async.wait_group 0;");
    __syncthreads();

    // add bias
    #pragma unroll
    for (int ni = 0; ni < 8; ni++) {
        int gn = n0 + wn + ni * 8 + ((lane & 3) << 1);
        float b0 = __ldg(&bias[gn]);
        float b1 = __ldg(&bias[gn + 1]);
        #pragma unroll
        for (int mi = 0; mi < 4; mi++) {
            acc[mi][ni][0] += b0; acc[mi][ni][1] += b1;
            acc[mi][ni][2] += b0; acc[mi][ni][3] += b1;
        }
    }

    const int sec = blockIdx.x / 12;        // 36 col-blocks: 12 per section
    if (sec == 2) {
        // V: plain store
        #pragma unroll
        for (int ni = 0; ni < 8; ni++) {
            int gn = n0 + wn + ni * 8 + ((lane & 3) << 1);
            #pragma unroll
            for (int mi = 0; mi < 4; mi++) {
                int gm = m0 + wm + mi * 16 + (lane >> 2);
                *reinterpret_cast<float2*>(&out[(size_t)gm * N_OUT + gn]) =
                    make_float2(acc[mi][ni][0], acc[mi][ni][1]);
                *reinterpret_cast<float2*>(&out[(size_t)(gm + 8) * N_OUT + gn]) =
                    make_float2(acc[mi][ni][2], acc[mi][ni][3]);
            }
        }
    } else {
        const float* gamma = sec ? nk : nq;
        float* sred = (float*)smem;         // [8 warps][64 rows]

        // per-thread ssq for 8 row-slots (mi x half), over this warp's 64 cols
        float ssq[4][2];
        #pragma unroll
        for (int mi = 0; mi < 4; mi++) {
            float s0 = 0.0f, s1 = 0.0f;
            #pragma unroll
            for (int ni = 0; ni < 8; ni++) {
                s0 = fmaf(acc[mi][ni][0], acc[mi][ni][0], s0);
                s0 = fmaf(acc[mi][ni][1], acc[mi][ni][1], s0);
                s1 = fmaf(acc[mi][ni][2], acc[mi][ni][2], s1);
                s1 = fmaf(acc[mi][ni][3], acc[mi][ni][3], s1);
            }
            ssq[mi][0] = s0; ssq[mi][1] = s1;
        }
        // reduce over the 4 lanes sharing a row (lane&3)
        #pragma unroll
        for (int mi = 0; mi < 4; mi++)
            #pragma unroll
            for (int h = 0; h < 2; h++) {
                ssq[mi][h] += __shfl_xor_sync(0xffffffffu, ssq[mi][h], 1);
                ssq[mi][h] += __shfl_xor_sync(0xffffffffu, ssq[mi][h], 2);
            }
        // exchange with partner warp (w^1): same rows, other 64 cols of the head
        if ((lane & 3) == 0) {
            #pragma unroll
            for (int mi = 0; mi < 4; mi++)
                #pragma unroll
                for (int h = 0; h < 2; h++)
                    sred[w * 64 + mi * 16 + h * 8 + (lane >> 2)] = ssq[mi][h];
        }
        __syncthreads();
        float rn[4][2];
        #pragma unroll
        for (int mi = 0; mi < 4; mi++)
            #pragma unroll
            for (int h = 0; h < 2; h++) {
                float tot = ssq[mi][h] + sred[(w ^ 1) * 64 + mi * 16 + h * 8 + (lane >> 2)];
                rn[mi][h] = rsqrtf(tot * (1.0f / 128.0f) + 1e-6f);
            }

        // normalize + rope + store
        #pragma unroll
        for (int ni = 0; ni < 8; ni++) {
            int gn   = n0 + wn + ni * 8 + ((lane & 3) << 1);
            int dcol = gn & 127;            // col within head (heads at 128-multiples)
            float g0 = __ldg(&gamma[dcol]);
            float g1 = __ldg(&gamma[dcol + 1]);
            #pragma unroll
            for (int mi = 0; mi < 4; mi++) {
                #pragma unroll
                for (int h = 0; h < 2; h++) {
                    int gm = m0 + wm + mi * 16 + h * 8 + (lane >> 2);
                    float e = acc[mi][ni][h * 2 + 0] * rn[mi][h] * g0;
                    float o = acc[mi][ni][h * 2 + 1] * rn[mi][h] * g1;
                    float cth = __ldg(&rot[(size_t)gm * 128 + dcol]);
                    float sth = __ldg(&rot[(size_t)gm * 128 + dcol + 1]);
                    *reinterpret_cast<float2*>(&out[(size_t)gm * N_OUT + gn]) =
                        make_float2(e * cth - o * sth, e * sth + o * cth);
                }
            }
        }
    }
}

// ---------------- launch ----------------
extern "C" void kernel_launch(void* const* d_in, const int* in_sizes, int n_in,
                              void* d_out, int out_size) {
    const float*  x      = (const float*)d_in[0];
    const void*   qw     = d_in[1];
    const float*  wsc    = (const float*)d_in[2];
    const float*  bias   = (const float*)d_in[3];
    const float*  ldn    = (const float*)d_in[4];
    const float*  lup    = (const float*)d_in[5];
    const float*  smooth = (const float*)d_in[6];
    const float*  nq     = (const float*)d_in[7];
    const float*  nk     = (const float*)d_in[8];
    const float*  rot    = (const float*)d_in[9];
    float* out = (float*)d_out;

    detect_qw_kernel<<<1, 256>>>((const int*)qw);

    {
        int tot = N_OUT * (K_IN / 2);
        dequant_w_kernel<<<(tot + 255) / 256, 256>>>(qw, wsc);
        lora_w_kernel<<<N_OUT, RANK>>>(lup);
    }
    cudaFuncSetAttribute(quant_act_kernel,
                         cudaFuncAttributeMaxDynamicSharedMemorySize, QA_SMEM);
    quant_act_kernel<<<M_TOK / TOK4, 256, QA_SMEM>>>(x, smooth, ldn);

    cudaFuncSetAttribute(gemm_kernel,
                         cudaFuncAttributeMaxDynamicSharedMemorySize, SMEM_TOTAL);
    {
        dim3 grid(N_OUT / BN, M_TOK / BM);   // (36, 32)
        gemm_kernel<<<grid, 256, SMEM_TOTAL>>>(out, bias, nq, nk, rot);
    }
}